// round 7
// baseline (speedup 1.0000x reference)
#include <cuda_runtime.h>
#include <cuda_bf16.h>
#include <math.h>

// LandmarkLoss: B=16, N=4096, flow [B,2,W,H] with W=H=1024.
// loss = sum over valid points of (x1+o0-x2)^2 + (y1+o1-y2)^2, / (2B)
// Reference's EXACT (non-standard) bilinear weights:
//   wa = (x1-x1d)*(y1-y1d)
//   wb = (x1u-x1)*(y1u-x1)   <- uses x1, faithful to source
//   wc = (x1u-x1)*(y1-y1d)
//   wd = (x1-x1d)*(y1u-x1)   <- uses x1, faithful to source
//
// R7: R1 hot path (1 thread/point, 8 gathers up-front, 256-thr blocks)
// + L2 evict_last via createpolicy + ld.global.nc.L2::cache_hint
//   (the ONLY scalar-load form ptxas accepts on sm_100; direct
//    .L2::evict_last qualifier is vector-256b-only -> R6 compile fail)
// + single kernel node (ticket + last-block tail), no init kernel.

#define LB 16
#define LN 4096
#define LW 1024
#define LH 1024

#define NTHREADS 256
#define NPOINTS (LB * LN)                       // 65536
#define NBLOCKS (NPOINTS / NTHREADS)            // 256

__device__ float ll_partials[NBLOCKS];
__device__ unsigned int ll_ticket = 0;

__device__ __forceinline__ unsigned long long mk_evict_last_policy() {
    unsigned long long pol;
    asm("createpolicy.fractional.L2::evict_last.b64 %0, 1.0;" : "=l"(pol));
    return pol;
}

__device__ __forceinline__ float ldg_hint(const float* p, unsigned long long pol) {
    float v;
    asm("ld.global.nc.L2::cache_hint.f32 %0, [%1], %2;"
        : "=f"(v) : "l"(p), "l"(pol));
    return v;
}

__global__ __launch_bounds__(NTHREADS) void ll_loss_kernel(
    const float* __restrict__ lm,     // [B,N,4]
    const float* __restrict__ flow,   // [B,2,W,H]
    float* __restrict__ out)
{
    int i = blockIdx.x * NTHREADS + threadIdx.x;   // exactly NPOINTS threads

    int b = i >> 12;  // / LN
    float4 l = reinterpret_cast<const float4*>(lm)[i];
    float x1 = l.x, y1 = l.y;

    float x1d = floorf(x1);
    float y1d = floorf(y1);
    float x1u = x1d + 1.0f;
    float y1u = y1d + 1.0f;

    bool valid = (x1u < (float)LW) && (y1u < (float)LH);

    int xd = (int)x1d; xd = max(0, min(xd, LW - 2));
    int yd = (int)y1d; yd = max(0, min(yd, LH - 2));

    const float* f0 = flow + (size_t)b * (2 * LW * LH); // channel 0
    const float* f1 = f0 + (LW * LH);                   // channel 1

    int idx_dd = xd * LH + yd;    // (xd, yd)
    int idx_du = idx_dd + 1;      // (xd, yu)
    int idx_ud = idx_dd + LH;     // (xu, yd)
    int idx_uu = idx_ud + 1;      // (xu, yu)

    unsigned long long pol = mk_evict_last_policy();

    // All 8 gathers issued up-front for maximum per-warp MLP.
    float a0 = ldg_hint(f0 + idx_dd, pol);
    float b0 = ldg_hint(f0 + idx_uu, pol);
    float c0 = ldg_hint(f0 + idx_ud, pol);
    float d0 = ldg_hint(f0 + idx_du, pol);
    float a1 = ldg_hint(f1 + idx_dd, pol);
    float b1 = ldg_hint(f1 + idx_uu, pol);
    float c1 = ldg_hint(f1 + idx_ud, pol);
    float d1 = ldg_hint(f1 + idx_du, pol);

    float wa = (x1 - x1d) * (y1 - y1d);
    float wb = (x1u - x1) * (y1u - x1);  // faithful to source
    float wc = (x1u - x1) * (y1 - y1d);
    float wd = (x1 - x1d) * (y1u - x1);  // faithful to source

    float o0 = fmaf(a0, wa, fmaf(b0, wb, fmaf(c0, wc, d0 * wd)));
    float o1 = fmaf(a1, wa, fmaf(b1, wb, fmaf(c1, wc, d1 * wd)));

    float dx = (x1 - l.z) + o0;
    float dy = (y1 - l.w) + o1;
    float pp = fmaf(dx, dx, dy * dy);
    float acc = valid ? pp : 0.0f;

    // ---- block reduction (8 warps) ----
    #pragma unroll
    for (int o = 16; o > 0; o >>= 1)
        acc += __shfl_down_sync(0xFFFFFFFFu, acc, o);

    __shared__ float s[NTHREADS / 32];
    __shared__ bool is_last;
    int lane = threadIdx.x & 31;
    int wid  = threadIdx.x >> 5;
    if (lane == 0) s[wid] = acc;
    __syncthreads();

    if (threadIdx.x == 0) {
        float bs = 0.0f;
        #pragma unroll
        for (int w = 0; w < NTHREADS / 32; w++) bs += s[w];
        ll_partials[blockIdx.x] = bs;
        __threadfence();
        unsigned int t = atomicAdd(&ll_ticket, 1u);
        is_last = (t == NBLOCKS - 1);
    }
    __syncthreads();

    // ---- last block: final reduction over 256 partials ----
    if (is_last) {
        float v = ll_partials[threadIdx.x];   // NTHREADS == NBLOCKS == 256
        #pragma unroll
        for (int o = 16; o > 0; o >>= 1)
            v += __shfl_down_sync(0xFFFFFFFFu, v, o);
        if (lane == 0) s[wid] = v;
        __syncthreads();
        if (threadIdx.x == 0) {
            float total = 0.0f;
            #pragma unroll
            for (int w = 0; w < NTHREADS / 32; w++) total += s[w];
            out[0] = total * (1.0f / (2.0f * (float)LB));
            ll_ticket = 0;   // reset for next graph replay
        }
    }
}

extern "C" void kernel_launch(void* const* d_in, const int* in_sizes, int n_in,
                              void* d_out, int out_size)
{
    const float* lm   = (const float*)d_in[0];  // landmarks [B,N,4]
    const float* flow = (const float*)d_in[1];  // flow [B,2,W,H]
    float* out = (float*)d_out;

    ll_loss_kernel<<<NBLOCKS, NTHREADS>>>(lm, flow, out);
}

// round 10
// speedup vs baseline: 1.0487x; 1.0487x over previous
#include <cuda_runtime.h>
#include <cuda_bf16.h>
#include <math.h>

// LandmarkLoss: B=16, N=4096, flow [B,2,W,H] with W=H=1024.
// loss = sum over valid points of (x1+o0-x2)^2 + (y1+o1-y2)^2, / (2B)
// Reference's EXACT (non-standard) bilinear weights:
//   wa = (x1-x1d)*(y1-y1d)
//   wb = (x1u-x1)*(y1u-x1)   <- uses x1, faithful to source
//   wc = (x1u-x1)*(y1-y1d)
//   wd = (x1-x1d)*(y1u-x1)   <- uses x1, faithful to source
//
// R10 = third submission of the R8 theory (R8/R9 hit broker infra flakes;
// R6 proved compile errors surface separately, so content is not the cause).
//  - R1 hot path: 1 thread/point, 8 __ldg gathers up-front, 256x256 launch.
//  - Single kernel node: block sums atomicAdd into one __device__ scalar;
//    ticketed last block does O(1) tail (scale + store + reset).
//  - Tail read/reset via atomics (atomicAdd(.,0) / atomicExch): compiler-
//    reorder-proof without volatile or inline asm.

#define LB 16
#define LN 4096
#define LW 1024
#define LH 1024

#define NTHREADS 256
#define NPOINTS (LB * LN)                       // 65536
#define NBLOCKS (NPOINTS / NTHREADS)            // 256

__device__ float ll_sum = 0.0f;
__device__ unsigned int ll_ticket = 0;

__global__ __launch_bounds__(NTHREADS) void ll_loss_kernel(
    const float* __restrict__ lm,     // [B,N,4]
    const float* __restrict__ flow,   // [B,2,W,H]
    float* __restrict__ out)
{
    int i = blockIdx.x * NTHREADS + threadIdx.x;   // exactly NPOINTS threads

    int b = i >> 12;  // / LN
    float4 l = reinterpret_cast<const float4*>(lm)[i];
    float x1 = l.x, y1 = l.y;

    float x1d = floorf(x1);
    float y1d = floorf(y1);
    float x1u = x1d + 1.0f;
    float y1u = y1d + 1.0f;

    bool valid = (x1u < (float)LW) && (y1u < (float)LH);

    int xd = (int)x1d; xd = max(0, min(xd, LW - 2));
    int yd = (int)y1d; yd = max(0, min(yd, LH - 2));

    const float* f0 = flow + (size_t)b * (2 * LW * LH); // channel 0
    const float* f1 = f0 + (LW * LH);                   // channel 1

    int idx_dd = xd * LH + yd;    // (xd, yd)
    int idx_du = idx_dd + 1;      // (xd, yu)
    int idx_ud = idx_dd + LH;     // (xu, yd)
    int idx_uu = idx_ud + 1;      // (xu, yu)

    // All 8 gathers issued up-front for maximum per-warp MLP.
    float a0 = __ldg(f0 + idx_dd);
    float b0 = __ldg(f0 + idx_uu);
    float c0 = __ldg(f0 + idx_ud);
    float d0 = __ldg(f0 + idx_du);
    float a1 = __ldg(f1 + idx_dd);
    float b1 = __ldg(f1 + idx_uu);
    float c1 = __ldg(f1 + idx_ud);
    float d1 = __ldg(f1 + idx_du);

    float wa = (x1 - x1d) * (y1 - y1d);
    float wb = (x1u - x1) * (y1u - x1);  // faithful to source
    float wc = (x1u - x1) * (y1 - y1d);
    float wd = (x1 - x1d) * (y1u - x1);  // faithful to source

    float o0 = fmaf(a0, wa, fmaf(b0, wb, fmaf(c0, wc, d0 * wd)));
    float o1 = fmaf(a1, wa, fmaf(b1, wb, fmaf(c1, wc, d1 * wd)));

    float dx = (x1 - l.z) + o0;
    float dy = (y1 - l.w) + o1;
    float pp = fmaf(dx, dx, dy * dy);
    float acc = valid ? pp : 0.0f;

    // ---- block reduction (8 warps) ----
    #pragma unroll
    for (int o = 16; o > 0; o >>= 1)
        acc += __shfl_down_sync(0xFFFFFFFFu, acc, o);

    __shared__ float s[NTHREADS / 32];
    int lane = threadIdx.x & 31;
    int wid  = threadIdx.x >> 5;
    if (lane == 0) s[wid] = acc;
    __syncthreads();

    if (threadIdx.x == 0) {
        float bs = 0.0f;
        #pragma unroll
        for (int w = 0; w < NTHREADS / 32; w++) bs += s[w];
        atomicAdd(&ll_sum, bs);
        __threadfence();
        unsigned int t = atomicAdd(&ll_ticket, 1u);
        if (t == NBLOCKS - 1) {
            // All NBLOCKS atomicAdds to ll_sum precede their ticket bumps
            // (threadfence + L2-coherent atomics), so ll_sum is complete.
            float total = atomicAdd(&ll_sum, 0.0f);   // ordered L2 read
            out[0] = total * (1.0f / (2.0f * (float)LB));
            atomicExch(&ll_sum, 0.0f);                // reset for next replay
            atomicExch(&ll_ticket, 0u);               // reset for next replay
        }
    }
}

extern "C" void kernel_launch(void* const* d_in, const int* in_sizes, int n_in,
                              void* d_out, int out_size)
{
    const float* lm   = (const float*)d_in[0];  // landmarks [B,N,4]
    const float* flow = (const float*)d_in[1];  // flow [B,2,W,H]
    float* out = (float*)d_out;

    ll_loss_kernel<<<NBLOCKS, NTHREADS>>>(lm, flow, out);
}